// round 17
// baseline (speedup 1.0000x reference)
#include <cuda_runtime.h>
#include <cuda_bf16.h>
#include <mma.h>
#include <math.h>
#include <stdint.h>

using namespace nvcuda;

#define BS 4
#define NQ 6000
#define NV 13294
#define EMB 256
#define NH 8
#define HD 32

#define MV (BS * NV)          // 53176
#define MQ (BS * NQ)          // 24000
#define MV_PAD 53248          // 416 * 128
#define MQ_PAD 24064          // 188 * 128

#define T_VALV 416            // value-proj CTAs (128x256 tiles)
#define T_OFF 376             // (MQ_PAD/128) * 2
#define T_AW  188             // (MQ_PAD/128) * 1
#define T_QP  (T_OFF + T_AW)  // 564

// Scratch (device globals: allocation-free per harness rules).
__device__ __nv_bfloat16 g_qb  [(size_t)MQ_PAD * EMB];  // query, bf16
__device__ __nv_bfloat16 g_wv  [256 * 256];             // W_val  bf16 [K][N]
__device__ __nv_bfloat16 g_wof [256 * 256];             // W_off  bf16 [K][N]
__device__ __nv_bfloat16 g_wat [256 * 128];             // W_attn bf16 [K][N]
__device__ __nv_bfloat16 g_wo  [256 * 256];             // W_out  bf16 [K][N]
__device__ __nv_bfloat16 g_vb  [(size_t)NH * MV_PAD * HD];  // value proj, HEAD-MAJOR [h][pix][32]
__device__ float         g_off [(size_t)MQ_PAD * 256];  // sampling offsets
__device__ float         g_aw  [(size_t)MQ_PAD * 128];  // attn logits
__device__ __nv_bfloat16 g_mid [(size_t)MQ_PAD * 256];  // aggregated heads (bf16)
__device__ float         g_brep[4 * 16 * 256];          // 16-row-replicated bias tiles

// ---------------------------------------------------------------------------
// Conversion: query f32->bf16, weights f32->bf16, replicated bias tiles.
// (value conversion is fused into the value GEMM.)
// ---------------------------------------------------------------------------
#define S_QRY (MQ * 64)
#define S_W   16384
#define S_WA  8192
#define S_CVT (S_QRY + 3 * S_W + S_WA)
#define S_TOT (S_CVT + 4096)

__global__ void cvt_all(const float* __restrict__ query,
                        const float* __restrict__ Wv, const float* __restrict__ Wof,
                        const float* __restrict__ Wat, const float* __restrict__ Wo,
                        const float* __restrict__ b0, const float* __restrict__ b1,
                        const float* __restrict__ b2, const float* __restrict__ b3)
{
    int i = blockIdx.x * blockDim.x + threadIdx.x;
    if (i >= S_TOT) return;
    if (i >= S_CVT) {                 // bias tile segment (stays f32)
        int j = i - S_CVT;
        int t = j >> 10;
        int c4 = j & 63;
        const float* b = (t == 0) ? b0 : (t == 1) ? b1 : (t == 2) ? b2 : b3;
        int col4 = (t == 2) ? (c4 & 31) : c4;
        ((float4*)g_brep)[j] = ((const float4*)b)[col4];
        return;
    }
    const float* src; __nv_bfloat16* dst;
    int j = i;
    if (j < S_QRY) { src = query; dst = g_qb; }
    else { j -= S_QRY;
        if (j < S_W) { src = Wv; dst = g_wv; }
        else { j -= S_W;
            if (j < S_W) { src = Wof; dst = g_wof; }
            else { j -= S_W;
                if (j < S_WA) { src = Wat; dst = g_wat; }
                else { j -= S_WA; src = Wo; dst = g_wo; } } } }
    float4 v = ((const float4*)src)[j];
    __nv_bfloat162 t0 = __floats2bfloat162_rn(v.x, v.y);
    __nv_bfloat162 t1 = __floats2bfloat162_rn(v.z, v.w);
    uint2 o; o.x = *(uint32_t*)&t0; o.y = *(uint32_t*)&t1;
    ((uint2*)dst)[j] = o;
}

// ---------------------------------------------------------------------------
// Common helpers
// ---------------------------------------------------------------------------
__device__ __forceinline__ void cp16(void* dst_smem, const void* src, int src_bytes)
{
    uint32_t d = (uint32_t)__cvta_generic_to_shared(dst_smem);
    asm volatile("cp.async.cg.shared.global [%0], [%1], 16, %2;\n"
                 :: "r"(d), "l"(src), "r"(src_bytes));
}
template<int N> __device__ __forceinline__ void cpwait()
{
    asm volatile("cp.async.wait_group %0;\n" :: "n"(N));
}
__device__ __forceinline__ uint2 pack4(float4 v)
{
    __nv_bfloat162 lo = __floats2bfloat162_rn(v.x, v.y);
    __nv_bfloat162 hi = __floats2bfloat162_rn(v.z, v.w);
    uint2 o; o.x = *(uint32_t*)&lo; o.y = *(uint32_t*)&hi;
    return o;
}
__device__ __forceinline__ uint32_t bfdup(float w)
{
    __nv_bfloat162 h = __floats2bfloat162_rn(w, w);
    return *(uint32_t*)&h;
}

// ---------------------------------------------------------------------------
// R11 GEMM core (256 threads, 8 warps 4x2, tile 128x128, BK=32, 4-stage).
// ---------------------------------------------------------------------------
#define AROW 40
#define BROW 136
#define A_ST (128 * AROW)
#define B_ST (32 * BROW)
#define NSTG 4
#define GEMM_SMEM (NSTG * (A_ST + B_ST) * 2)   // 75776 bytes

struct GemmCore {
    __nv_bfloat16* As; __nv_bfloat16* Bsm;
    int tid, lane, wid, warp_m, warp_n, row0, col0;
    wmma::fragment<wmma::accumulator, 16, 16, 16, float> acc[2][4];

    __device__ __forceinline__ void init(char* sm, int r0, int c0, const float* brep)
    {
        As = (__nv_bfloat16*)sm; Bsm = As + NSTG * A_ST;
        tid = threadIdx.x; lane = tid & 31; wid = tid >> 5;
        warp_m = wid >> 1; warp_n = wid & 1;
        row0 = r0; col0 = c0;
#pragma unroll
        for (int i = 0; i < 2; i++)
#pragma unroll
            for (int j = 0; j < 4; j++)
                wmma::load_matrix_sync(acc[i][j],
                    brep + col0 + warp_n * 64 + j * 16, 256, wmma::mem_row_major);
    }

    __device__ __forceinline__ void prefetch(const __nv_bfloat16* A, const __nv_bfloat16* B,
                                             int M, int N, int K, int k0, int st)
    {
        const int am = tid >> 2, ac = tid & 3;
        const int bk = tid >> 4, bc = tid & 15;
#pragma unroll
        for (int it = 0; it < 2; it++) {
            int m = am + it * 64;
            int r = row0 + m;
            cp16(&As[st * A_ST + m * AROW + ac * 8],
                 A + (size_t)r * K + k0 + ac * 8, (r < M) ? 16 : 0);
        }
#pragma unroll
        for (int it = 0; it < 2; it++) {
            int k = bk + it * 16;
            cp16(&Bsm[st * B_ST + k * BROW + bc * 8],
                 B + (size_t)(k0 + k) * N + col0 + bc * 8, 16);
        }
        asm volatile("cp.async.commit_group;\n");
    }

    __device__ __forceinline__ void compute_stage(int st)
    {
        const __nv_bfloat16* as = As + st * A_ST;
        const __nv_bfloat16* bs = Bsm + st * B_ST;
#pragma unroll
        for (int kk = 0; kk < 2; kk++) {
            wmma::fragment<wmma::matrix_a, 16, 16, 16, __nv_bfloat16, wmma::row_major> a[2];
            wmma::fragment<wmma::matrix_b, 16, 16, 16, __nv_bfloat16, wmma::row_major> b[4];
#pragma unroll
            for (int ii = 0; ii < 2; ii++)
                wmma::load_matrix_sync(a[ii], as + (warp_m * 32 + ii * 16) * AROW + kk * 16, AROW);
#pragma unroll
            for (int j = 0; j < 4; j++)
                wmma::load_matrix_sync(b[j], bs + (kk * 16) * BROW + warp_n * 64 + j * 16, BROW);
#pragma unroll
            for (int ii = 0; ii < 2; ii++)
#pragma unroll
                for (int j = 0; j < 4; j++)
                    wmma::mma_sync(acc[ii][j], a[ii], b[j], acc[ii][j]);
        }
    }

    template<int ITERS>
    __device__ __forceinline__ void mainloop(const __nv_bfloat16* A, const __nv_bfloat16* B,
                                             int M, int N, int K)
    {
        prefetch(A, B, M, N, K, 0,  0);
        prefetch(A, B, M, N, K, 32, 1);
        prefetch(A, B, M, N, K, 64, 2);
#pragma unroll
        for (int i = 0; i < ITERS; i++) {
            if (i < ITERS - 2)       cpwait<2>();
            else if (i == ITERS - 2) cpwait<1>();
            else                     cpwait<0>();
            __syncthreads();
            if (i + 3 < ITERS)
                prefetch(A, B, M, N, K, (i + 3) * 32, (i + 3) & 3);
            compute_stage(i & 3);
        }
    }

    __device__ __forceinline__ void store_f32(float* C, const float* resid, int N, int Mstore)
    {
        if ((row0 + warp_m * 32) >= Mstore) return;
#pragma unroll
        for (int i = 0; i < 2; i++)
#pragma unroll
            for (int j = 0; j < 4; j++) {
                size_t off = (size_t)(row0 + warp_m * 32 + i * 16) * N + col0 + warp_n * 64 + j * 16;
                if (resid) {
                    wmma::fragment<wmma::accumulator, 16, 16, 16, float> r;
                    wmma::load_matrix_sync(r, resid + off, N, wmma::mem_row_major);
#pragma unroll
                    for (int t = 0; t < r.num_elements; t++)
                        acc[i][j].x[t] += r.x[t];
                }
                wmma::store_matrix_sync(C + off, acc[i][j], N, wmma::mem_row_major);
            }
    }
};

// ---------------------------------------------------------------------------
// Value projection: 512 threads, tile 128x256 (FULL N -> value read once),
// A = f32 value with in-register bf16 conversion (distance-2 reg prefetch),
// B = g_wv via 4-stage cp.async. 16 warps (4x4), warp tile 32x64.
// Epilogue: bf16 HEAD-MAJOR scatter into g_vb.
// ---------------------------------------------------------------------------
#define BROW_V 264
#define B_STV (32 * BROW_V)
#define VAL_SMEM ((2 * A_ST + 4 * B_STV) * 2)   // 88064 bytes

__global__ __launch_bounds__(512, 1)
void gemm_value(const float* __restrict__ value, const float* __restrict__ brep)
{
    extern __shared__ char smc[];
    __nv_bfloat16* As  = (__nv_bfloat16*)smc;               // 2 stages
    __nv_bfloat16* Bsm = As + 2 * A_ST;                     // 4 stages

    const int tid = threadIdx.x;
    const int lane = tid & 31;
    const int wid = tid >> 5;
    const int warp_m = wid >> 2;      // 0..3
    const int warp_n = wid & 3;       // 0..3
    const int row0 = blockIdx.x * 128;

    wmma::fragment<wmma::accumulator, 16, 16, 16, float> acc[2][4];
#pragma unroll
    for (int i = 0; i < 2; i++)
#pragma unroll
        for (int j = 0; j < 4; j++)
            wmma::load_matrix_sync(acc[i][j],
                brep + warp_n * 64 + j * 16, 256, wmma::mem_row_major);

    auto prefetchB = [&](int k0, int st) {
#pragma unroll
        for (int it = 0; it < 2; it++) {
            int idx = tid + it * 512;       // 0..1023
            int k = idx >> 5, c = idx & 31;
            cp16(&Bsm[st * B_STV + k * BROW_V + c * 8],
                 g_wv + (size_t)(k0 + k) * 256 + c * 8, 16);
        }
        asm volatile("cp.async.commit_group;\n");
    };
    const int arow = tid >> 2, acol = (tid & 3) * 8;
    auto ldgA = [&](int k0, uint2* r) {
        int gr = row0 + arow;
        if (gr < MV) {
            const float4* src = (const float4*)(value + (size_t)gr * 256 + k0 + acol);
            r[0] = pack4(src[0]);
            r[1] = pack4(src[1]);
        } else {
            r[0] = make_uint2(0u, 0u);
            r[1] = make_uint2(0u, 0u);
        }
    };
    auto stsA = [&](const uint2* r, int st) {
        uint4 w; w.x = r[0].x; w.y = r[0].y; w.z = r[1].x; w.w = r[1].y;
        *(uint4*)(As + st * A_ST + arow * AROW + acol) = w;
    };

    uint2 ar[2][2];
    ldgA(0,  ar[0]);
    ldgA(32, ar[1]);
    prefetchB(0,  0);
    prefetchB(32, 1);
    prefetchB(64, 2);

#pragma unroll
    for (int i = 0; i < 8; i++) {
        stsA(ar[i & 1], i & 1);
        if (i + 2 < 8) ldgA((i + 2) * 32, ar[i & 1]);
        if (i + 3 < 8) prefetchB((i + 3) * 32, (i + 3) & 3);
        if (i < 6)      cpwait<3>();
        else if (i == 6) cpwait<1>();
        else             cpwait<0>();
        __syncthreads();
        {
            const __nv_bfloat16* as = As + (i & 1) * A_ST;
            const __nv_bfloat16* bs = Bsm + (i & 3) * B_STV;
#pragma unroll
            for (int kk = 0; kk < 2; kk++) {
                wmma::fragment<wmma::matrix_a, 16, 16, 16, __nv_bfloat16, wmma::row_major> a[2];
                wmma::fragment<wmma::matrix_b, 16, 16, 16, __nv_bfloat16, wmma::row_major> b[4];
#pragma unroll
                for (int ii = 0; ii < 2; ii++)
                    wmma::load_matrix_sync(a[ii], as + (warp_m * 32 + ii * 16) * AROW + kk * 16, AROW);
#pragma unroll
                for (int j = 0; j < 4; j++)
                    wmma::load_matrix_sync(b[j], bs + (kk * 16) * BROW_V + warp_n * 64 + j * 16, BROW_V);
#pragma unroll
                for (int ii = 0; ii < 2; ii++)
#pragma unroll
                    for (int j = 0; j < 4; j++)
                        wmma::mma_sync(acc[ii][j], a[ii], b[j], acc[ii][j]);
            }
        }
        __syncthreads();
    }

    float* scratch = (float*)smc + wid * 256;
#pragma unroll
    for (int i = 0; i < 2; i++)
#pragma unroll
        for (int j = 0; j < 4; j++) {
            __syncwarp();
            wmma::store_matrix_sync(scratch, acc[i][j], 16, wmma::mem_row_major);
            __syncwarp();
            int r = lane >> 1, cb = (lane & 1) * 8;
            const float* sp = scratch + r * 16 + cb;
            float4 f0 = *(const float4*)sp;
            float4 f1 = *(const float4*)(sp + 4);
            uint2 lo = pack4(f0), hi = pack4(f1);
            uint4 o; o.x = lo.x; o.y = lo.y; o.z = hi.x; o.w = hi.y;
            int grow = row0 + warp_m * 32 + i * 16 + r;
            int gcol = warp_n * 64 + j * 16 + cb;
            size_t off = (size_t)(gcol >> 5) * (MV_PAD * HD) + (size_t)grow * HD + (gcol & 31);
            *(uint4*)(g_vb + off) = o;
        }
}

// ---------------------------------------------------------------------------
// Query projections (off + attn) in one flat launch; A = g_qb (bf16).
// ---------------------------------------------------------------------------
__global__ __launch_bounds__(256, 2)
void gemm_qproj(const float* __restrict__ brep)
{
    extern __shared__ char smc[];
    int t = blockIdx.x;

    const __nv_bfloat16* B;
    const float* brp;
    int N, row_t, col_t, prob;
    if (t < T_OFF) {
        prob = 0; B = g_wof; brp = brep + 4096;
        N = 256; row_t = t >> 1; col_t = t & 1;
    } else {
        int u = t - T_OFF;
        prob = 1; B = g_wat; brp = brep + 2 * 4096;
        N = 128; row_t = u; col_t = 0;
    }

    GemmCore g;
    g.init(smc, row_t * 128, col_t * 128, brp);
    g.mainloop<8>(g_qb, B, MQ, N, 256);

    if (prob == 0) g.store_f32(g_off, nullptr, 256, MQ_PAD);
    else           g.store_f32(g_aw,  nullptr, 128, MQ_PAD);
}

// ---------------------------------------------------------------------------
// Output projection + bias + fp32 residual (R11 path)
// ---------------------------------------------------------------------------
__global__ __launch_bounds__(256, 2)
void gemm_out(const float* __restrict__ brep, const float* __restrict__ query,
              float* __restrict__ out)
{
    extern __shared__ char smc[];
    GemmCore g;
    g.init(smc, blockIdx.y * 128, blockIdx.x * 128, brep + 3 * 4096);
    g.mainloop<8>(g_mid, g_wo, MQ, 256, 256);
    g.store_f32(out, query, 256, MQ);
}

// ---------------------------------------------------------------------------
// Fused sampling: TWO (b,q,h) units per warp (16 lanes each).
// Phase 1: softmax + corner metadata; weight stored PRE-PACKED as bf16x2 {w,w}.
//   Meta layout is CORNER-MAJOR: meta[uloc][corner][pt] so phase 2 loads
//   two points' {idx, w} with one LDS.128.
// Phase 2: lane = {unit|corner|chanquad}; per point: one LDG.128 (8 bf16
//   channels) + 4 fma.rn.bf16x2 (no unpacking!). bf16 partials flushed to
//   fp32 every 4 points to bound rounding. Cross-corner shfl reduction.
// ---------------------------------------------------------------------------
#define HSTRIDE (MV_PAD * HD)

__global__ __launch_bounds__(256)
void sample_fused(const float* __restrict__ refp)
{
    __shared__ int2 meta[16][4][16];   // [unit][corner][pt] = 8 KB

    const int warp = (blockIdx.x * blockDim.x + threadIdx.x) >> 5;
    const int lane = threadIdx.x & 31;
    const int half = lane >> 4;
    const int unit = warp * 2 + half;
    const int uloc = (threadIdx.x >> 5) * 2 + half;

    const int h  = unit & 7;
    const int bq = unit >> 3;
    const int b  = bq / NQ;

    // ---- Phase 1 ----
    {
        const int p = lane & 15;
        const float* awp = g_aw + bq * 128 + h * 16;
        float a = awp[p];
        float m = a;
#pragma unroll
        for (int o = 8; o; o >>= 1) m = fmaxf(m, __shfl_xor_sync(0xffffffffu, m, o));
        float e = __expf(a - m);
        float s = e;
#pragma unroll
        for (int o = 8; o; o >>= 1) s += __shfl_xor_sync(0xffffffffu, s, o);
        const float wp = e / s;

        const int l = p >> 2;
        const int W = (0x0D193264 >> (l * 8)) & 0xFF;               // 100,50,25,13
        const long long spack = 0LL | (10000LL << 14) | (12500LL << 28) | (13125LL << 42);
        const int START = (int)((spack >> (14 * l)) & 0x3FFF);      // 0,10000,12500,13125

        const float* offp = g_off + bq * 256 + h * 32;
        float rx = refp[bq * 8 + 2 * l];
        float ry = refp[bq * 8 + 2 * l + 1];

        float x = fmaf(rx, (float)W, offp[2 * p]) - 0.5f;
        float y = fmaf(ry, (float)W, offp[2 * p + 1]) - 0.5f;
        float xf = floorf(x), yf = floorf(y);
        int   x0 = (int)xf,  y0 = (int)yf;
        float wx1 = x - xf, wy1 = y - yf;
        float wx0 = 1.f - wx1, wy0 = 1.f - wy1;

        // padding_mode='zeros': fold OOB validity into the weights
        wx0 *= (float)(x0 >= 0 && x0 < W);
        wx1 *= (float)(x0 >= -1 && x0 < W - 1);
        wy0 *= (float)(y0 >= 0 && y0 < W);
        wy1 *= (float)(y0 >= -1 && y0 < W - 1);

        int xc0 = min(max(x0, 0), W - 1);
        int xc1 = min(max(x0 + 1, 0), W - 1);
        int yc0 = min(max(y0, 0), W - 1);
        int yc1 = min(max(y0 + 1, 0), W - 1);

        const int hb   = h * HSTRIDE;
        const int base = b * NV + START;
        int r0 = hb + (base + yc0 * W) * HD;
        int r1 = hb + (base + yc1 * W) * HD;

        meta[uloc][0][p] = make_int2(r0 + xc0 * HD, (int)bfdup(wp * wy0 * wx0));
        meta[uloc][1][p] = make_int2(r0 + xc1 * HD, (int)bfdup(wp * wy0 * wx1));
        meta[uloc][2][p] = make_int2(r1 + xc0 * HD, (int)bfdup(wp * wy1 * wx0));
        meta[uloc][3][p] = make_int2(r1 + xc1 * HD, (int)bfdup(wp * wy1 * wx1));
    }
    __syncwarp();

    // ---- Phase 2: bf16x2-FMA gather ----
    const int corner = (lane >> 2) & 3;
    const int sub    = lane & 3;
    const __nv_bfloat16* vbp = g_vb + sub * 8;
    const int4* mrow = (const int4*)&meta[uloc][corner][0];   // 8 x {idx0,w0,idx1,w1}

    float f0 = 0.f, f1 = 0.f, f2 = 0.f, f3 = 0.f, f4 = 0.f, f5 = 0.f, f6 = 0.f, f7 = 0.f;
#pragma unroll
    for (int g = 0; g < 4; g++) {          // 4 groups of 4 points
        uint32_t b0 = 0u, b1 = 0u, b2 = 0u, b3 = 0u;   // bf16x2 partials
#pragma unroll
        for (int q = 0; q < 2; q++) {      // 2 int4 = 4 points
            int4 md = mrow[g * 2 + q];
            uint4 ra = *(const uint4*)(vbp + md.x);
            uint32_t wa = (uint32_t)md.y;
            asm("fma.rn.bf16x2 %0, %1, %2, %0;" : "+r"(b0) : "r"(ra.x), "r"(wa));
            asm("fma.rn.bf16x2 %0, %1, %2, %0;" : "+r"(b1) : "r"(ra.y), "r"(wa));
            asm("fma.rn.bf16x2 %0, %1, %2, %0;" : "+r"(b2) : "r"(ra.z), "r"(wa));
            asm("fma.rn.bf16x2 %0, %1, %2, %0;" : "+r"(b3) : "r"(ra.w), "r"(wa));
            uint4 rb = *(const uint4*)(vbp + md.z);
            uint32_t wb = (uint32_t)md.w;
            asm("fma.rn.bf16x2 %0, %1, %2, %0;" : "+r"(b0) : "r"(rb.x), "r"(wb));
            asm("fma.rn.bf16x2 %0, %1, %2, %0;" : "+r"(b1) : "r"(rb.y), "r"(wb));
            asm("fma.rn.bf16x2 %0, %1, %2, %0;" : "+r"(b2) : "r"(rb.z), "r"(wb));
            asm("fma.rn.bf16x2 %0, %1, %2, %0;" : "+r"(b3) : "r"(rb.w), "r"(wb));
        }
        // flush bf16 partials into fp32 accumulators
        float2 t;
        t = __bfloat1622float2(*(__nv_bfloat162*)&b0); f0 += t.x; f1 += t.y;
        t = __bfloat1622float2(*(__nv_bfloat162*)&b1); f2 += t.x; f3 += t.y;
        t = __bfloat1622float2(*(__nv_bfloat162*)&b2); f4 += t.x; f5 += t.y;
        t = __bfloat1622float2(*(__nv_bfloat162*)&b3); f6 += t.x; f7 += t.y;
    }

    // reduce across the 4 corner lanes (xor 4, 8) within each 16-lane half
#pragma unroll
    for (int o = 4; o <= 8; o <<= 1) {
        f0 += __shfl_xor_sync(0xffffffffu, f0, o);
        f1 += __shfl_xor_sync(0xffffffffu, f1, o);
        f2 += __shfl_xor_sync(0xffffffffu, f2, o);
        f3 += __shfl_xor_sync(0xffffffffu, f3, o);
        f4 += __shfl_xor_sync(0xffffffffu, f4, o);
        f5 += __shfl_xor_sync(0xffffffffu, f5, o);
        f6 += __shfl_xor_sync(0xffffffffu, f6, o);
        f7 += __shfl_xor_sync(0xffffffffu, f7, o);
    }
    if (corner == 0) {
        uint2 lo = pack4(make_float4(f0, f1, f2, f3));
        uint2 hi = pack4(make_float4(f4, f5, f6, f7));
        uint4 o; o.x = lo.x; o.y = lo.y; o.z = hi.x; o.w = hi.y;
        *(uint4*)&g_mid[bq * 256 + h * HD + sub * 8] = o;
    }
}

// ---------------------------------------------------------------------------
extern "C" void kernel_launch(void* const* d_in, const int* in_sizes, int n_in,
                              void* d_out, int out_size)
{
    const float* query  = (const float*)d_in[0];
    const float* value  = (const float*)d_in[1];
    const float* refp   = (const float*)d_in[2];
    const float* W_off  = (const float*)d_in[3];
    const float* b_off  = (const float*)d_in[4];
    const float* W_attn = (const float*)d_in[5];
    const float* b_attn = (const float*)d_in[6];
    const float* W_val  = (const float*)d_in[7];
    const float* b_val  = (const float*)d_in[8];
    const float* W_out  = (const float*)d_in[9];
    const float* b_out  = (const float*)d_in[10];
    float* out = (float*)d_out;

    float* pbrep;
    cudaGetSymbolAddress((void**)&pbrep, g_brep);

    cudaFuncSetAttribute(gemm_value, cudaFuncAttributeMaxDynamicSharedMemorySize, VAL_SMEM);
    cudaFuncSetAttribute(gemm_qproj, cudaFuncAttributeMaxDynamicSharedMemorySize, GEMM_SMEM);
    cudaFuncSetAttribute(gemm_out,   cudaFuncAttributeMaxDynamicSharedMemorySize, GEMM_SMEM);

    // 0) query/weights bf16 conversion + bias tiles (value cvt fused into GEMM)
    cvt_all<<<(S_TOT + 255) / 256, 256>>>(query, W_val, W_off, W_attn, W_out,
                                          b_val, b_off, b_attn, b_out);

    // 1) value projection: f32 A read once, converted in-flight, head-major bf16 out
    gemm_value<<<T_VALV, 512, VAL_SMEM>>>(value, pbrep);

    // 2) offset + attention projections (bf16 A)
    gemm_qproj<<<T_QP, 256, GEMM_SMEM>>>(pbrep);

    // 3) fused sampler: bf16x2-FMA gather
    sample_fused<<<(MQ * NH) / 16, 256>>>(refp);

    // 4) output projection + bias + fp32 residual
    gemm_out<<<dim3(2, MQ_PAD / 128), 256, GEMM_SMEM>>>(pbrep, query, out);
}